// round 5
// baseline (speedup 1.0000x reference)
#include <cuda_runtime.h>
#include <cuda_bf16.h>
#include <stdint.h>

// Problem constants (fixed by setup_inputs): N=4096 rows, D=512
#define NROW 4096
#define DDIM 512

// gram+KL tiling
#define BM 64
#define BN 128
#define BK 32
#define NSPLIT 2
#define JRANGE (NROW / NSPLIT)        // 2048 j per CTA
#define NJT (JRANGE / BN)             // 16 j-tiles per CTA
#define KSTEPS (DDIM / BK)            // 16 k-stages per j-tile
#define S_STAGES (NJT * KSTEPS)       // 256 flat stages

#define XI_PITCH 520                  // bf16 pitch for persistent i-tiles
#define ST_PITCH 40                   // bf16 pitch for streaming j-stage tiles (80B rows)

// dynamic smem layout (bytes)
#define XI_OFF 0
#define YI_OFF (BM * XI_PITCH * 2)                 // 66560
#define STAGE_OFF (2 * BM * XI_PITCH * 2)          // 133120
#define STAGE_TILE (BN * ST_PITCH * 2)             // 10240 (xj), yj at +10240
#define STAGE_BYTES (2 * STAGE_TILE)               // 20480 per stage
#define NSTAGE 4
#define SMEM_TOTAL (STAGE_OFF + NSTAGE * STAGE_BYTES)  // 215040

// ---------------- device scratch (allocation-free contract) ----------------
__device__ __align__(16) __nv_bfloat16 g_Xn[NROW * DDIM];
__device__ __align__(16) __nv_bfloat16 g_Yn[NROW * DDIM];
// per row: 8 partial slots (split*4 + wn) x {l_a, s, l_b}
__device__ float g_part[NROW * 24];

// ---------------- PTX helpers ----------------
__device__ __forceinline__ void ldm_x4(uint32_t &r0, uint32_t &r1, uint32_t &r2,
                                       uint32_t &r3, uint32_t addr) {
  asm volatile("ldmatrix.sync.aligned.m8n8.x4.shared.b16 {%0,%1,%2,%3}, [%4];\n"
               : "=r"(r0), "=r"(r1), "=r"(r2), "=r"(r3)
               : "r"(addr));
}

__device__ __forceinline__ void mma_bf16(float *c, const uint32_t *a,
                                         const uint32_t *b) {
  asm volatile(
      "mma.sync.aligned.m16n8k16.row.col.f32.bf16.bf16.f32 "
      "{%0,%1,%2,%3}, {%4,%5,%6,%7}, {%8,%9}, {%0,%1,%2,%3};\n"
      : "+f"(c[0]), "+f"(c[1]), "+f"(c[2]), "+f"(c[3])
      : "r"(a[0]), "r"(a[1]), "r"(a[2]), "r"(a[3]), "r"(b[0]), "r"(b[1]));
}

__device__ __forceinline__ void cp16(uint32_t saddr, const void *gaddr) {
  asm volatile("cp.async.cg.shared.global [%0], [%1], 16;\n" ::"r"(saddr),
               "l"(gaddr));
}
__device__ __forceinline__ void cp_commit() {
  asm volatile("cp.async.commit_group;\n");
}
template <int N> __device__ __forceinline__ void cp_wait() {
  asm volatile("cp.async.wait_group %0;\n" ::"n"(N));
}

// ---------------- 1) row-normalize fp32 -> bf16 ----------------
__global__ void normalize_kernel(const float *__restrict__ X,
                                 const float *__restrict__ Y) {
  const int row = blockIdx.x;
  const float *src = blockIdx.y ? Y : X;
  __nv_bfloat16 *dst = blockIdx.y ? g_Yn : g_Xn;
  const int tid = threadIdx.x;  // 128 threads, one float4 each

  float4 v = reinterpret_cast<const float4 *>(src)[row * (DDIM / 4) + tid];
  float ss = v.x * v.x + v.y * v.y + v.z * v.z + v.w * v.w;
#pragma unroll
  for (int o = 16; o > 0; o >>= 1) ss += __shfl_xor_sync(0xffffffffu, ss, o);
  __shared__ float wsum[4];
  if ((tid & 31) == 0) wsum[tid >> 5] = ss;
  __syncthreads();
  const float tot = wsum[0] + wsum[1] + wsum[2] + wsum[3];
  const float inv = 1.0f / fmaxf(sqrtf(tot), 1e-8f);

  __nv_bfloat162 p0 = __floats2bfloat162_rn(v.x * inv, v.y * inv);
  __nv_bfloat162 p1 = __floats2bfloat162_rn(v.z * inv, v.w * inv);
  uint2 packed;
  packed.x = *reinterpret_cast<uint32_t *>(&p0);
  packed.y = *reinterpret_cast<uint32_t *>(&p1);
  reinterpret_cast<uint2 *>(dst)[row * (DDIM / 4) + tid] = packed;
}

// ---------------- 2) fused gram + fixed-shift softmax-KL ----------------
extern __shared__ __align__(16) unsigned char smem_raw[];

__global__ void __launch_bounds__(256, 1) gram_kl_kernel() {
  const int tid = threadIdx.x;
  const int lane = tid & 31;
  const int wid = tid >> 5;
  const int wm = wid & 1;   // warp row group: rows wm*32
  const int wn = wid >> 1;  // warp col group: cols wn*32
  const int i0 = blockIdx.x * BM;
  const int split = blockIdx.y;
  const int j0 = split * JRANGE;

  const uint32_t smem_base = (uint32_t)__cvta_generic_to_shared(smem_raw);
  const uint32_t xi_base = smem_base + XI_OFF;
  const uint32_t yi_base = smem_base + YI_OFF;

  // ------- persistent Xi/Yi tiles (full D) via cp.async, group 0 -------
  {
    const int row = tid >> 2;
#pragma unroll
    for (int c = (tid & 3); c < DDIM / 8; c += 4) {  // 16B chunks (8 bf16)
      cp16(xi_base + row * (XI_PITCH * 2) + c * 16,
           &g_Xn[(i0 + row) * DDIM + c * 8]);
      cp16(yi_base + row * (XI_PITCH * 2) + c * 16,
           &g_Yn[(i0 + row) * DDIM + c * 8]);
    }
    cp_commit();
  }

  // streaming stage loader: 256 rows total (128 Xj + 128 Yj), 1 row/thread
  const int srow = tid & 127;
  const int ssel = tid >> 7;  // 0: Xj, 1: Yj
  const __nv_bfloat16 *sgl = ssel ? g_Yn : g_Xn;
  auto load_stage = [&](int s) {
    if (s < S_STAGES) {
      const int jt = s >> 4;
      const int k0 = (s & 15) * BK;
      const int j = j0 + jt * BN;
      const uint32_t st = smem_base + STAGE_OFF + (s & (NSTAGE - 1)) * STAGE_BYTES +
                          ssel * STAGE_TILE;
#pragma unroll
      for (int c = 0; c < BK / 8; c++) {
        cp16(st + srow * (ST_PITCH * 2) + c * 16,
             &sgl[(j + srow) * DDIM + k0 + c * 8]);
      }
    }
    cp_commit();  // always commit (group accounting, incl. empty tail groups)
  };

  load_stage(0);
  load_stage(1);
  load_stage(2);

  // ldmatrix coordinates (validated in R1/R2)
  const int a_r0 = wm * 32 + (lane & 15);          // A frag mf=0 rows
  const int a_col = (lane >> 4) * 8;
  const int b_rowoff = ((lane >> 4) << 3) + (lane & 7);
  const int b_col = ((lane >> 3) & 1) * 8;

  float accA[2][4][4], accB[2][4][4];
#pragma unroll
  for (int mf = 0; mf < 2; mf++)
#pragma unroll
    for (int n = 0; n < 4; n++)
#pragma unroll
      for (int r = 0; r < 4; r++) {
        accA[mf][n][r] = 0.f;
        accB[mf][n][r] = 0.f;
      }

  // KL accumulators: 4 fragment rows (mf*2 + h), each {l_a, s, l_b}
  float kla[4] = {0.f, 0.f, 0.f, 0.f};
  float kls[4] = {0.f, 0.f, 0.f, 0.f};
  float klb[4] = {0.f, 0.f, 0.f, 0.f};

  for (int s = 0; s < S_STAGES; s++) {
    cp_wait<2>();    // stage s (and persistent tiles at s==0) landed
    __syncthreads(); // also protects buffer (s+3)&3, consumed at stage s-1
    load_stage(s + 3);

    const uint32_t xj_b =
        smem_base + STAGE_OFF + (s & (NSTAGE - 1)) * STAGE_BYTES;
    const uint32_t yj_b = xj_b + STAGE_TILE;
    const int kabs = (s & 15) * BK;

#pragma unroll
    for (int kk = 0; kk < BK; kk += 16) {
      uint32_t ax[2][4], ay[2][4], bx[2][4], by[2][4];
      ldm_x4(ax[0][0], ax[0][1], ax[0][2], ax[0][3],
             xi_base + 2u * (a_r0 * XI_PITCH + kabs + kk + a_col));
      ldm_x4(ax[1][0], ax[1][1], ax[1][2], ax[1][3],
             xi_base + 2u * ((a_r0 + 16) * XI_PITCH + kabs + kk + a_col));
      ldm_x4(ay[0][0], ay[0][1], ay[0][2], ay[0][3],
             yi_base + 2u * (a_r0 * XI_PITCH + kabs + kk + a_col));
      ldm_x4(ay[1][0], ay[1][1], ay[1][2], ay[1][3],
             yi_base + 2u * ((a_r0 + 16) * XI_PITCH + kabs + kk + a_col));
#pragma unroll
      for (int g = 0; g < 2; g++) {
        const int brow = wn * 32 + g * 16 + b_rowoff;
        ldm_x4(bx[g][0], bx[g][1], bx[g][2], bx[g][3],
               xj_b + 2u * (brow * ST_PITCH + kk + b_col));
        ldm_x4(by[g][0], by[g][1], by[g][2], by[g][3],
               yj_b + 2u * (brow * ST_PITCH + kk + b_col));
      }
#pragma unroll
      for (int mf = 0; mf < 2; mf++)
#pragma unroll
        for (int g = 0; g < 2; g++) {
          mma_bf16(&accA[mf][2 * g + 0][0], ax[mf], &bx[g][0]);
          mma_bf16(&accA[mf][2 * g + 1][0], ax[mf], &bx[g][2]);
          mma_bf16(&accB[mf][2 * g + 0][0], ay[mf], &by[g][0]);
          mma_bf16(&accB[mf][2 * g + 1][0], ay[mf], &by[g][2]);
        }
    }

    if ((s & 15) == 15) {
      // register-only epilogue: logits a=-A, b=-B in [-1,1]; fixed shift 0.
#pragma unroll
      for (int mf = 0; mf < 2; mf++)
#pragma unroll
        for (int n = 0; n < 4; n++) {
#pragma unroll
          for (int h = 0; h < 2; h++) {
            const float A0 = accA[mf][n][2 * h + 0];
            const float A1 = accA[mf][n][2 * h + 1];
            const float B0 = accB[mf][n][2 * h + 0];
            const float B1 = accB[mf][n][2 * h + 1];
            const float e0 = __expf(-A0), e1 = __expf(-A1);
            kla[mf * 2 + h] += e0 + e1;
            kls[mf * 2 + h] += e0 * (B0 - A0) + e1 * (B1 - A1);
            klb[mf * 2 + h] += __expf(-B0) + __expf(-B1);
          }
#pragma unroll
          for (int r = 0; r < 4; r++) {
            accA[mf][n][r] = 0.f;
            accB[mf][n][r] = 0.f;
          }
        }
    }
  }

  // quad-reduce (lanes sharing a fragment row) and write partials
#pragma unroll
  for (int h = 0; h < 4; h++) {
#pragma unroll
    for (int o = 1; o <= 2; o <<= 1) {
      kla[h] += __shfl_xor_sync(0xffffffffu, kla[h], o);
      kls[h] += __shfl_xor_sync(0xffffffffu, kls[h], o);
      klb[h] += __shfl_xor_sync(0xffffffffu, klb[h], o);
    }
  }
  if ((lane & 3) == 0) {
    const int slot = (split * 4 + wn) * 3;
#pragma unroll
    for (int mf = 0; mf < 2; mf++)
#pragma unroll
      for (int h = 0; h < 2; h++) {
        const int row = i0 + wm * 32 + mf * 16 + h * 8 + (lane >> 2);
        g_part[row * 24 + slot + 0] = kla[mf * 2 + h];
        g_part[row * 24 + slot + 1] = kls[mf * 2 + h];
        g_part[row * 24 + slot + 2] = klb[mf * 2 + h];
      }
  }
}

// ---------------- 3) merge partials + deterministic mean ----------------
__global__ void merge_reduce_kernel(float *__restrict__ out) {
  __shared__ float red[1024];
  const int tid = threadIdx.x;
  float local = 0.f;
  for (int row = tid; row < NROW; row += 1024) {
    const float *p = &g_part[row * 24];
    float L = 0.f, S = 0.f, Lb = 0.f;
#pragma unroll
    for (int k = 0; k < 8; k++) {
      L += p[k * 3 + 0];
      S += p[k * 3 + 1];
      Lb += p[k * 3 + 2];
    }
    // kl_i = sum t*(a-b) - lse(a) + lse(b), fixed shift 0
    local += S / L - logf(L) + logf(Lb);
  }
  red[tid] = local;
  __syncthreads();
#pragma unroll
  for (int o = 512; o > 0; o >>= 1) {
    if (tid < o) red[tid] += red[tid + o];
    __syncthreads();
  }
  if (tid == 0) out[0] = red[0] / (float)NROW;
}

// ---------------- launch ----------------
extern "C" void kernel_launch(void *const *d_in, const int *in_sizes, int n_in,
                              void *d_out, int out_size) {
  const float *X = (const float *)d_in[0];  // cosine_distance_latent (target)
  const float *Y = (const float *)d_in[1];  // mse_latent (predicted)
  float *out = (float *)d_out;

  cudaFuncSetAttribute(gram_kl_kernel,
                       cudaFuncAttributeMaxDynamicSharedMemorySize, SMEM_TOTAL);

  normalize_kernel<<<dim3(NROW, 2), 128>>>(X, Y);
  gram_kl_kernel<<<dim3(NROW / BM, NSPLIT), 256, SMEM_TOTAL>>>();
  merge_reduce_kernel<<<1, 1024>>>(out);
}